// round 1
// baseline (speedup 1.0000x reference)
#include <cuda_runtime.h>

#define GENES 20000
#define NROWS 262144

// Scratch (allocation-free rule: __device__ globals)
__device__ float g_M[16 * 16 * 16];     // M[n][k][l]
__device__ float g_E3[GENES * 16];      // MLP output per gene
__device__ float g_U[GENES * 256];      // chunk-major: float4 at [g*64 + i*16 + n] = U[g][n][4i..4i+3]

// ---------------------------------------------------------------------------
// Kernel 1: M[n,k,l] = sum_m BD[n,m] * BW[n,m,k] * BW[m,n,l]
// ---------------------------------------------------------------------------
__global__ void k_M(const float* __restrict__ BW, const float* __restrict__ BD) {
    int idx = blockIdx.x * 256 + threadIdx.x;   // 16 blocks x 256 = 4096
    int l = idx & 15, k = (idx >> 4) & 15, n = idx >> 8;
    float s = 0.f;
#pragma unroll
    for (int m = 0; m < 16; m++)
        s = fmaf(BD[n * 16 + m] * BW[n * 256 + m * 16 + k], BW[m * 256 + n * 16 + l], s);
    g_M[idx] = s;
}

// ---------------------------------------------------------------------------
// Kernel 2: E3[g] = W3*relu(W2*relu(W1*emb[g]+b1)+b2)+b3   (one thread/gene)
// ---------------------------------------------------------------------------
__global__ void k_E3(const float* __restrict__ emb,
                     const float* __restrict__ W1, const float* __restrict__ b1,
                     const float* __restrict__ W2, const float* __restrict__ b2,
                     const float* __restrict__ W3, const float* __restrict__ b3) {
    __shared__ float sW1[256], sW2[256], sW3[256], sb[48];
    int t = threadIdx.x;
    sW1[t] = W1[t]; sW2[t] = W2[t]; sW3[t] = W3[t];
    if (t < 16) { sb[t] = b1[t]; sb[16 + t] = b2[t]; sb[32 + t] = b3[t]; }
    __syncthreads();
    int g = blockIdx.x * 256 + t;
    if (g >= GENES) return;

    float4 e4[4];
    const float4* ep = (const float4*)(emb + (size_t)g * 16);
    e4[0] = ep[0]; e4[1] = ep[1]; e4[2] = ep[2]; e4[3] = ep[3];
    float* v = (float*)e4;
    float w[16], h[16];

#pragma unroll
    for (int i = 0; i < 16; i++) {
        float s = sb[i];
#pragma unroll
        for (int j = 0; j < 16; j++) s = fmaf(sW1[i * 16 + j], v[j], s);
        w[i] = fmaxf(s, 0.f);
    }
#pragma unroll
    for (int i = 0; i < 16; i++) {
        float s = sb[16 + i];
#pragma unroll
        for (int j = 0; j < 16; j++) s = fmaf(sW2[i * 16 + j], w[j], s);
        h[i] = fmaxf(s, 0.f);
    }
#pragma unroll
    for (int i = 0; i < 16; i++) {
        float s = sb[32 + i];
#pragma unroll
        for (int j = 0; j < 16; j++) s = fmaf(sW3[i * 16 + j], h[j], s);
        w[i] = s;   // no relu on layer 3
    }
    float4* op = (float4*)(g_E3 + (size_t)g * 16);
    op[0] = make_float4(w[0], w[1], w[2], w[3]);
    op[1] = make_float4(w[4], w[5], w[6], w[7]);
    op[2] = make_float4(w[8], w[9], w[10], w[11]);
    op[3] = make_float4(w[12], w[13], w[14], w[15]);
}

// ---------------------------------------------------------------------------
// Kernel 3: U[g,n,k] = sum_l M[n,k,l] * E3[g,l]   (16 threads per gene, lane = n)
// M stored transposed in shared so lanes (varying n) read consecutive words.
// ---------------------------------------------------------------------------
__global__ void k_U() {
    __shared__ float sMt[4096];  // sMt[k*256 + l*16 + n] = M[n][k][l]
    int t = threadIdx.x;
#pragma unroll
    for (int i = t; i < 4096; i += 256) {
        int l = i & 15, k = (i >> 4) & 15, n = i >> 8;
        sMt[k * 256 + l * 16 + n] = g_M[i];
    }
    __syncthreads();

    int g = blockIdx.x * 16 + (t >> 4);
    int n = t & 15;
    float4 e4[4];
    const float4* ep = (const float4*)(g_E3 + (size_t)g * 16);
    e4[0] = ep[0]; e4[1] = ep[1]; e4[2] = ep[2]; e4[3] = ep[3];
    const float* e = (const float*)e4;

    float u[16];
#pragma unroll
    for (int k = 0; k < 16; k++) u[k] = 0.f;
#pragma unroll
    for (int l = 0; l < 16; l++) {
        float ev = e[l];
#pragma unroll
        for (int k = 0; k < 16; k++)
            u[k] = fmaf(sMt[k * 256 + l * 16 + n], ev, u[k]);
    }
    // chunk-major store: float4 at [g*64 + i*16 + n] holds u[4i..4i+3]
    float4* o = (float4*)(g_U + (size_t)g * 256);
    o[0 * 16 + n] = make_float4(u[0], u[1], u[2], u[3]);
    o[1 * 16 + n] = make_float4(u[4], u[5], u[6], u[7]);
    o[2 * 16 + n] = make_float4(u[8], u[9], u[10], u[11]);
    o[3 * 16 + n] = make_float4(u[12], u[13], u[14], u[15]);
}

// ---------------------------------------------------------------------------
// Kernel 4: main. 16 lanes per row (2 rows per warp), lane j owns z[n=j].
//   z[n] = E3[x0] . U[x1,n,:] + Boff[n]
//   y[j] = relu(Wc1[j,:] . z + bc1[j]);  out = sum_j Wc2[j] y[j] + bc2 + sum(phenos)
// ---------------------------------------------------------------------------
__global__ void k_main(const int* __restrict__ x, const float* __restrict__ phenos,
                       const float* __restrict__ Boff, const float* __restrict__ Wc1,
                       const float* __restrict__ bc1, const float* __restrict__ Wc2,
                       const float* __restrict__ bc2, float* __restrict__ out) {
    __shared__ float sWc1t[256];   // transposed: sWc1t[n*16+j] = Wc1[j*16+n]
    __shared__ float sP[49];       // [0:16) bc1, [16:32) Wc2, [32:48) Boff, [48] bc2
    __shared__ float sz[256];
    int t = threadIdx.x;
    { int j = t & 15, n = t >> 4; sWc1t[n * 16 + j] = Wc1[j * 16 + n]; }
    if (t < 16) { sP[t] = bc1[t]; sP[16 + t] = Wc2[t]; sP[32 + t] = Boff[t]; }
    if (t == 0) sP[48] = bc2[0];
    __syncthreads();

    int j = t & 15;
    int row = blockIdx.x * 16 + (t >> 4);

    int2 xi = ((const int2*)x)[row];
    const float4* U4 = (const float4*)(g_U + (size_t)xi.y * 256);
    const float4* E4 = (const float4*)(g_E3 + (size_t)xi.x * 16);
    float4 a0 = E4[0], a1 = E4[1], a2 = E4[2], a3 = E4[3];
    float4 u0 = U4[j], u1 = U4[16 + j], u2 = U4[32 + j], u3 = U4[48 + j];

    float z = sP[32 + j];
    z = fmaf(a0.x, u0.x, z); z = fmaf(a0.y, u0.y, z); z = fmaf(a0.z, u0.z, z); z = fmaf(a0.w, u0.w, z);
    z = fmaf(a1.x, u1.x, z); z = fmaf(a1.y, u1.y, z); z = fmaf(a1.z, u1.z, z); z = fmaf(a1.w, u1.w, z);
    z = fmaf(a2.x, u2.x, z); z = fmaf(a2.y, u2.y, z); z = fmaf(a2.z, u2.z, z); z = fmaf(a2.w, u2.w, z);
    z = fmaf(a3.x, u3.x, z); z = fmaf(a3.y, u3.y, z); z = fmaf(a3.z, u3.z, z); z = fmaf(a3.w, u3.w, z);

    sz[t] = z;        // t = group*16 + j
    __syncwarp();

    float acc = sP[j];
    const float* zb = sz + (t & ~15);
#pragma unroll
    for (int n = 0; n < 16; n++) acc = fmaf(zb[n], sWc1t[n * 16 + j], acc);
    acc = fmaxf(acc, 0.f) * sP[16 + j];

    acc += __shfl_xor_sync(0xffffffffu, acc, 8);
    acc += __shfl_xor_sync(0xffffffffu, acc, 4);
    acc += __shfl_xor_sync(0xffffffffu, acc, 2);
    acc += __shfl_xor_sync(0xffffffffu, acc, 1);

    if (j == 0) {
        float2 ph = ((const float2*)phenos)[row];
        out[row] = acc + sP[48] + ph.x + ph.y;
    }
}

// ---------------------------------------------------------------------------
extern "C" void kernel_launch(void* const* d_in, const int* in_sizes, int n_in,
                              void* d_out, int out_size) {
    const int*   x      = (const int*)d_in[0];
    const float* phenos = (const float*)d_in[1];
    const float* emb    = (const float*)d_in[2];
    const float* W1 = (const float*)d_in[3],  *b1 = (const float*)d_in[4];
    const float* W2 = (const float*)d_in[5],  *b2 = (const float*)d_in[6];
    const float* W3 = (const float*)d_in[7],  *b3 = (const float*)d_in[8];
    const float* BW = (const float*)d_in[9],  *BD = (const float*)d_in[10];
    const float* Boff = (const float*)d_in[11];
    const float* Wc1 = (const float*)d_in[12], *bc1 = (const float*)d_in[13];
    const float* Wc2 = (const float*)d_in[14], *bc2 = (const float*)d_in[15];
    float* out = (float*)d_out;

    k_M<<<16, 256>>>(BW, BD);
    k_E3<<<(GENES + 255) / 256, 256>>>(emb, W1, b1, W2, b2, W3, b3);
    k_U<<<GENES / 16, 256>>>();
    k_main<<<NROWS / 16, 256>>>(x, phenos, Boff, Wc1, bc1, Wc2, bc2, out);
}

// round 2
// speedup vs baseline: 1.2389x; 1.2389x over previous
#include <cuda_runtime.h>

#define D 16

// Scratch (allocation-free rule: __device__ globals)
__device__ float g_MW[16 * 16 * 16];      // MW[j][k][l] = sum_n Wc1[j,n] * M[n,k,l]
__device__ float g_bb[16];                // bb[j] = bc1[j] + sum_n Wc1[j,n]*Boff[n]
__device__ float g_E3[20000 * 16];        // MLP output per gene
__device__ float g_UW[20000 * 256];       // chunk-major: float4 at [g*64 + i*16 + j] = UW[g][j][4i..4i+3]

// ---------------------------------------------------------------------------
// Kernel 1 (fused): block 0 computes MW + bb; blocks 1.. compute E3 per gene.
//   M[n,k,l]  = sum_m BD[n,m] * BW[n,m,k] * BW[m,n,l]
//   MW[j,k,l] = sum_n Wc1[j,n] * M[n,k,l]
// ---------------------------------------------------------------------------
__global__ void k_pre(const float* __restrict__ BW, const float* __restrict__ BD,
                      const float* __restrict__ Wc1, const float* __restrict__ bc1,
                      const float* __restrict__ Boff,
                      const float* __restrict__ emb,
                      const float* __restrict__ W1, const float* __restrict__ b1,
                      const float* __restrict__ W2, const float* __restrict__ b2,
                      const float* __restrict__ W3, const float* __restrict__ b3,
                      int genes) {
    int t = threadIdx.x;
    if (blockIdx.x == 0) {
        __shared__ float sM[4096];
#pragma unroll
        for (int i = t; i < 4096; i += 256) {
            int l = i & 15, k = (i >> 4) & 15, n = i >> 8;
            float s = 0.f;
#pragma unroll
            for (int m = 0; m < 16; m++)
                s = fmaf(BD[n * 16 + m] * BW[n * 256 + m * 16 + k], BW[m * 256 + n * 16 + l], s);
            sM[i] = s;
        }
        __syncthreads();
#pragma unroll
        for (int i = t; i < 4096; i += 256) {
            int l = i & 15, k = (i >> 4) & 15, j = i >> 8;
            float s = 0.f;
#pragma unroll
            for (int n = 0; n < 16; n++)
                s = fmaf(Wc1[j * 16 + n], sM[n * 256 + k * 16 + l], s);
            g_MW[i] = s;
        }
        if (t < 16) {
            float s = bc1[t];
#pragma unroll
            for (int n = 0; n < 16; n++) s = fmaf(Wc1[t * 16 + n], Boff[n], s);
            g_bb[t] = s;
        }
        return;
    }

    // ---- E3 path: gene-level 3-layer MLP ----
    __shared__ float sW1[256], sW2[256], sW3[256], sb[48];
    sW1[t] = W1[t]; sW2[t] = W2[t]; sW3[t] = W3[t];
    if (t < 16) { sb[t] = b1[t]; sb[16 + t] = b2[t]; sb[32 + t] = b3[t]; }
    __syncthreads();
    int g = (blockIdx.x - 1) * 256 + t;
    if (g >= genes) return;

    float4 e4[4];
    const float4* ep = (const float4*)(emb + (size_t)g * 16);
    e4[0] = ep[0]; e4[1] = ep[1]; e4[2] = ep[2]; e4[3] = ep[3];
    float* v = (float*)e4;
    float w[16], h[16];
#pragma unroll
    for (int i = 0; i < 16; i++) {
        float s = sb[i];
#pragma unroll
        for (int jj = 0; jj < 16; jj++) s = fmaf(sW1[i * 16 + jj], v[jj], s);
        w[i] = fmaxf(s, 0.f);
    }
#pragma unroll
    for (int i = 0; i < 16; i++) {
        float s = sb[16 + i];
#pragma unroll
        for (int jj = 0; jj < 16; jj++) s = fmaf(sW2[i * 16 + jj], w[jj], s);
        h[i] = fmaxf(s, 0.f);
    }
#pragma unroll
    for (int i = 0; i < 16; i++) {
        float s = sb[32 + i];
#pragma unroll
        for (int jj = 0; jj < 16; jj++) s = fmaf(sW3[i * 16 + jj], h[jj], s);
        w[i] = s;   // no relu on layer 3
    }
    float4* op = (float4*)(g_E3 + (size_t)g * 16);
    op[0] = make_float4(w[0], w[1], w[2], w[3]);
    op[1] = make_float4(w[4], w[5], w[6], w[7]);
    op[2] = make_float4(w[8], w[9], w[10], w[11]);
    op[3] = make_float4(w[12], w[13], w[14], w[15]);
}

// ---------------------------------------------------------------------------
// Kernel 2: UW[g,j,k] = sum_l MW[j,k,l] * E3[g,l]   (16 threads/gene, lane = j)
// Shared transpose padded (stride 17) for conflict-free STS and LDS.
// ---------------------------------------------------------------------------
__global__ void k_U(int genes) {
    __shared__ float sMWt[4352];  // sMWt[k*272 + l*17 + j] = MW[j][k][l]
    int t = threadIdx.x;
#pragma unroll
    for (int i = t; i < 4096; i += 256) {
        int l = i & 15, k = (i >> 4) & 15, j = i >> 8;
        sMWt[k * 272 + l * 17 + j] = g_MW[i];
    }
    __syncthreads();

    int g = blockIdx.x * 16 + (t >> 4);
    if (g >= genes) return;
    int j = t & 15;
    float4 e4[4];
    const float4* ep = (const float4*)(g_E3 + (size_t)g * 16);
    e4[0] = ep[0]; e4[1] = ep[1]; e4[2] = ep[2]; e4[3] = ep[3];
    const float* e = (const float*)e4;

    float u[16];
#pragma unroll
    for (int k = 0; k < 16; k++) u[k] = 0.f;
#pragma unroll
    for (int l = 0; l < 16; l++) {
        float ev = e[l];
#pragma unroll
        for (int k = 0; k < 16; k++)
            u[k] = fmaf(sMWt[k * 272 + l * 17 + j], ev, u[k]);
    }
    float4* o = (float4*)(g_UW + (size_t)g * 256);
    o[0 * 16 + j] = make_float4(u[0], u[1], u[2], u[3]);
    o[1 * 16 + j] = make_float4(u[4], u[5], u[6], u[7]);
    o[2 * 16 + j] = make_float4(u[8], u[9], u[10], u[11]);
    o[3 * 16 + j] = make_float4(u[12], u[13], u[14], u[15]);
}

// ---------------------------------------------------------------------------
// Kernel 3: main. 16 lanes per row (2 rows/warp), lane j owns classifier unit j.
//   y_j = relu(E3[x0] . UW[x1,j,:] + bb[j]);  out = sum_j Wc2[j]*y_j + bc2 + sum(phenos)
// ---------------------------------------------------------------------------
__global__ void k_main(const int* __restrict__ x, const float* __restrict__ phenos,
                       const float* __restrict__ Wc2, const float* __restrict__ bc2,
                       float* __restrict__ out) {
    int t = threadIdx.x;
    int j = t & 15;
    int row = blockIdx.x * 16 + (t >> 4);

    int2 xi = ((const int2*)x)[row];
    const float4* U4 = (const float4*)(g_UW + (size_t)xi.y * 256);
    const float4* E4 = (const float4*)(g_E3 + (size_t)xi.x * 16);
    float4 a0 = E4[0], a1 = E4[1], a2 = E4[2], a3 = E4[3];
    float4 u0 = U4[j], u1 = U4[16 + j], u2 = U4[32 + j], u3 = U4[48 + j];

    float z = g_bb[j];
    z = fmaf(a0.x, u0.x, z); z = fmaf(a0.y, u0.y, z); z = fmaf(a0.z, u0.z, z); z = fmaf(a0.w, u0.w, z);
    z = fmaf(a1.x, u1.x, z); z = fmaf(a1.y, u1.y, z); z = fmaf(a1.z, u1.z, z); z = fmaf(a1.w, u1.w, z);
    z = fmaf(a2.x, u2.x, z); z = fmaf(a2.y, u2.y, z); z = fmaf(a2.z, u2.z, z); z = fmaf(a2.w, u2.w, z);
    z = fmaf(a3.x, u3.x, z); z = fmaf(a3.y, u3.y, z); z = fmaf(a3.z, u3.z, z); z = fmaf(a3.w, u3.w, z);

    float acc = fmaxf(z, 0.f) * Wc2[j];
    acc += __shfl_xor_sync(0xffffffffu, acc, 8);
    acc += __shfl_xor_sync(0xffffffffu, acc, 4);
    acc += __shfl_xor_sync(0xffffffffu, acc, 2);
    acc += __shfl_xor_sync(0xffffffffu, acc, 1);

    if (j == 0) {
        float2 ph = ((const float2*)phenos)[row];
        out[row] = acc + bc2[0] + ph.x + ph.y;
    }
}

// ---------------------------------------------------------------------------
extern "C" void kernel_launch(void* const* d_in, const int* in_sizes, int n_in,
                              void* d_out, int out_size) {
    const int*   x      = (const int*)d_in[0];
    const float* phenos = (const float*)d_in[1];
    const float* emb    = (const float*)d_in[2];
    const float* W1 = (const float*)d_in[3],  *b1 = (const float*)d_in[4];
    const float* W2 = (const float*)d_in[5],  *b2 = (const float*)d_in[6];
    const float* W3 = (const float*)d_in[7],  *b3 = (const float*)d_in[8];
    const float* BW = (const float*)d_in[9],  *BD = (const float*)d_in[10];
    const float* Boff = (const float*)d_in[11];
    const float* Wc1 = (const float*)d_in[12], *bc1 = (const float*)d_in[13];
    const float* Wc2 = (const float*)d_in[14], *bc2 = (const float*)d_in[15];
    float* out = (float*)d_out;

    int rows  = in_sizes[0] / 2;     // 262144
    int genes = in_sizes[2] / D;     // 20000

    k_pre<<<1 + (genes + 255) / 256, 256>>>(BW, BD, Wc1, bc1, Boff, emb,
                                            W1, b1, W2, b2, W3, b3, genes);
    k_U<<<(genes + 15) / 16, 256>>>(genes);
    k_main<<<rows / 16, 256>>>(x, phenos, Wc2, bc2, out);
}

// round 3
// speedup vs baseline: 1.2771x; 1.0309x over previous
#include <cuda_runtime.h>

#define D 16
#define GBLK 64

// Scratch (allocation-free rule: __device__ globals)
__device__ float g_MW[4096];              // MW[j][k][l] = sum_n Wc1[j,n] * M[n,k,l]
__device__ float g_bb[16];                // bb[j] = bc1[j] + sum_n Wc1[j,n]*Boff[n]
__device__ float g_E3[20000 * 16];        // MLP output per gene
__device__ float g_UW[20000 * 256];       // chunk-major: float4 at [g*64 + i*16 + j] = UW[g][j][4i..4i+3]

// ---------------------------------------------------------------------------
// Kernel 1: MW[j,k,l] = sum_n sum_m Wc1[j,n]*BD[n,m]*BW[n,m,k]*BW[m,n,l]
//           bb[j]     = bc1[j] + sum_n Wc1[j,n]*Boff[n]
// 16 blocks x 256 threads, one output element per thread. All operand tensors
// are tiny (<=16KB) so the repeated loads are L1 hits.
// ---------------------------------------------------------------------------
__global__ void k_mw(const float* __restrict__ BW, const float* __restrict__ BD,
                     const float* __restrict__ Wc1, const float* __restrict__ bc1,
                     const float* __restrict__ Boff) {
    int idx = blockIdx.x * 256 + threadIdx.x;   // 4096 threads
    int l = idx & 15, k = (idx >> 4) & 15, j = idx >> 8;
    float s = 0.f;
#pragma unroll
    for (int n = 0; n < 16; n++) {
        float wjn = Wc1[j * 16 + n];
#pragma unroll
        for (int m = 0; m < 16; m++) {
            float p = BD[n * 16 + m] * BW[n * 256 + m * 16 + k];
            s = fmaf(wjn * p, BW[m * 256 + n * 16 + l], s);
        }
    }
    g_MW[idx] = s;

    if (blockIdx.x == 0 && threadIdx.x < 16) {
        int jj = threadIdx.x;
        float b = bc1[jj];
#pragma unroll
        for (int n = 0; n < 16; n++) b = fmaf(Wc1[jj * 16 + n], Boff[n], b);
        g_bb[jj] = b;
    }
}

// ---------------------------------------------------------------------------
// Kernel 2 (fused E3 + UW), 64 genes per 256-thread block.
// Phase 1 (MLP): 16 lanes per gene; lane i keeps W1/W2/W3 row i in registers,
//   v broadcast via width-16 shuffles. No LDS in the layer loops.
// Phase 2 (UW): thread owns (j = t&15, kchunk c = (t>>4)&3); its 64 MW weights
//   live in registers; streams 16 genes (subgroup t>>6 interleaving) from
//   padded shared. Per gene: 16 broadcast LDS + 64 FMA + 1 STG.128.
// ---------------------------------------------------------------------------
__global__ void k_e3uw(const float* __restrict__ emb,
                       const float* __restrict__ W1, const float* __restrict__ b1,
                       const float* __restrict__ W2, const float* __restrict__ b2,
                       const float* __restrict__ W3, const float* __restrict__ b3,
                       int genes) {
    __shared__ float sv[GBLK * 17];   // padded stride 17: conflict-free 4-way broadcast
    int t = threadIdx.x;
    int lane = t & 15;
    int base = blockIdx.x * GBLK;

    // --- load W rows into registers (broadcast across 16-lane groups) ---
    float w1r[16], w2r[16], w3r[16];
    {
        const float4* r1 = (const float4*)(W1 + lane * 16);
        const float4* r2 = (const float4*)(W2 + lane * 16);
        const float4* r3 = (const float4*)(W3 + lane * 16);
#pragma unroll
        for (int q = 0; q < 4; q++) {
            float4 a = r1[q]; w1r[q*4+0]=a.x; w1r[q*4+1]=a.y; w1r[q*4+2]=a.z; w1r[q*4+3]=a.w;
            float4 b = r2[q]; w2r[q*4+0]=b.x; w2r[q*4+1]=b.y; w2r[q*4+2]=b.z; w2r[q*4+3]=b.w;
            float4 c = r3[q]; w3r[q*4+0]=c.x; w3r[q*4+1]=c.y; w3r[q*4+2]=c.z; w3r[q*4+3]=c.w;
        }
    }
    float bias1 = b1[lane], bias2 = b2[lane], bias3 = b3[lane];

    // --- Phase 1: MLP, 4 iterations of 16 genes (16 lanes each) ---
#pragma unroll
    for (int it = 0; it < 4; it++) {
        int glocal = (t >> 4) + 16 * it;
        int g = base + glocal;
        int gc = (g < genes) ? g : (genes - 1);
        float v = emb[(size_t)gc * 16 + lane];

        float h = bias1;
#pragma unroll
        for (int jj = 0; jj < 16; jj++)
            h = fmaf(w1r[jj], __shfl_sync(0xffffffffu, v, jj, 16), h);
        v = fmaxf(h, 0.f);
        h = bias2;
#pragma unroll
        for (int jj = 0; jj < 16; jj++)
            h = fmaf(w2r[jj], __shfl_sync(0xffffffffu, v, jj, 16), h);
        v = fmaxf(h, 0.f);
        h = bias3;
#pragma unroll
        for (int jj = 0; jj < 16; jj++)
            h = fmaf(w3r[jj], __shfl_sync(0xffffffffu, v, jj, 16), h);
        // no relu on layer 3
        sv[glocal * 17 + lane] = h;
        if (g < genes) g_E3[(size_t)g * 16 + lane] = h;
    }
    __syncthreads();

    // --- Phase 2: UW. thread = (j, kchunk c, gene subgroup s) ---
    int j = t & 15;
    int c = (t >> 4) & 3;
    int sg = t >> 6;                 // 0..3

    float mw[64];                    // MW[j][c*4+kk][l], contiguous in g_MW
    {
        const float4* mp = (const float4*)(g_MW + j * 256 + c * 64);
#pragma unroll
        for (int q = 0; q < 16; q++) {
            float4 m4 = mp[q];
            mw[q*4+0]=m4.x; mw[q*4+1]=m4.y; mw[q*4+2]=m4.z; mw[q*4+3]=m4.w;
        }
    }

    float4* outp = (float4*)g_UW;
#pragma unroll
    for (int gi = 0; gi < 16; gi++) {
        int gl = gi * 4 + sg;
        int g = base + gl;
        float u0 = 0.f, u1 = 0.f, u2 = 0.f, u3 = 0.f;
#pragma unroll
        for (int l = 0; l < 16; l++) {
            float ev = sv[gl * 17 + l];
            u0 = fmaf(mw[0  + l], ev, u0);
            u1 = fmaf(mw[16 + l], ev, u1);
            u2 = fmaf(mw[32 + l], ev, u2);
            u3 = fmaf(mw[48 + l], ev, u3);
        }
        if (g < genes)
            outp[(size_t)g * 64 + c * 16 + j] = make_float4(u0, u1, u2, u3);
    }
}

// ---------------------------------------------------------------------------
// Kernel 3: main. 16 lanes per row (2 rows/warp), lane j owns classifier unit j.
//   y_j = relu(E3[x0] . UW[x1,j,:] + bb[j]);  out = sum_j Wc2[j]*y_j + bc2 + sum(phenos)
// ---------------------------------------------------------------------------
__global__ void k_main(const int* __restrict__ x, const float* __restrict__ phenos,
                       const float* __restrict__ Wc2, const float* __restrict__ bc2,
                       float* __restrict__ out) {
    int t = threadIdx.x;
    int j = t & 15;
    int row = blockIdx.x * 16 + (t >> 4);

    int2 xi = ((const int2*)x)[row];
    const float4* U4 = (const float4*)(g_UW + (size_t)xi.y * 256);
    const float4* E4 = (const float4*)(g_E3 + (size_t)xi.x * 16);
    float4 a0 = E4[0], a1 = E4[1], a2 = E4[2], a3 = E4[3];
    float4 u0 = U4[j], u1 = U4[16 + j], u2 = U4[32 + j], u3 = U4[48 + j];

    float z = g_bb[j];
    z = fmaf(a0.x, u0.x, z); z = fmaf(a0.y, u0.y, z); z = fmaf(a0.z, u0.z, z); z = fmaf(a0.w, u0.w, z);
    z = fmaf(a1.x, u1.x, z); z = fmaf(a1.y, u1.y, z); z = fmaf(a1.z, u1.z, z); z = fmaf(a1.w, u1.w, z);
    z = fmaf(a2.x, u2.x, z); z = fmaf(a2.y, u2.y, z); z = fmaf(a2.z, u2.z, z); z = fmaf(a2.w, u2.w, z);
    z = fmaf(a3.x, u3.x, z); z = fmaf(a3.y, u3.y, z); z = fmaf(a3.z, u3.z, z); z = fmaf(a3.w, u3.w, z);

    float acc = fmaxf(z, 0.f) * Wc2[j];
    acc += __shfl_xor_sync(0xffffffffu, acc, 8);
    acc += __shfl_xor_sync(0xffffffffu, acc, 4);
    acc += __shfl_xor_sync(0xffffffffu, acc, 2);
    acc += __shfl_xor_sync(0xffffffffu, acc, 1);

    if (j == 0) {
        float2 ph = ((const float2*)phenos)[row];
        out[row] = acc + bc2[0] + ph.x + ph.y;
    }
}

// ---------------------------------------------------------------------------
extern "C" void kernel_launch(void* const* d_in, const int* in_sizes, int n_in,
                              void* d_out, int out_size) {
    const int*   x      = (const int*)d_in[0];
    const float* phenos = (const float*)d_in[1];
    const float* emb    = (const float*)d_in[2];
    const float* W1 = (const float*)d_in[3],  *b1 = (const float*)d_in[4];
    const float* W2 = (const float*)d_in[5],  *b2 = (const float*)d_in[6];
    const float* W3 = (const float*)d_in[7],  *b3 = (const float*)d_in[8];
    const float* BW = (const float*)d_in[9],  *BD = (const float*)d_in[10];
    const float* Boff = (const float*)d_in[11];
    const float* Wc1 = (const float*)d_in[12], *bc1 = (const float*)d_in[13];
    const float* Wc2 = (const float*)d_in[14], *bc2 = (const float*)d_in[15];
    float* out = (float*)d_out;

    int rows  = in_sizes[0] / 2;     // 262144
    int genes = in_sizes[2] / D;     // 20000

    k_mw<<<16, 256>>>(BW, BD, Wc1, bc1, Boff);
    k_e3uw<<<(genes + GBLK - 1) / GBLK, 256>>>(emb, W1, b1, W2, b2, W3, b3, genes);
    k_main<<<rows / 16, 256>>>(x, phenos, Wc2, bc2, out);
}

// round 4
// speedup vs baseline: 1.7057x; 1.3355x over previous
#include <cuda_runtime.h>
#include <cuda_fp16.h>

#define D 16
#define GBLK 64

// Scratch (allocation-free rule: __device__ globals). uint4-typed for 16B alignment.
__device__ float g_MW[4096];              // MW[j][k][l] = sum_n Wc1[j,n] * M[n,k,l]
__device__ float g_bb[16];                // bb[j] = bc1[j] + sum_n Wc1[j,n]*Boff[n]
__device__ uint4 g_E3h[20000 * 2];        // half[16] per gene (MLP output)
__device__ uint4 g_UWh[20000 * 32];       // half: uint2 at [g*64 + c*16 + j] = UW[g][j][4c..4c+3]

// ---------------------------------------------------------------------------
// Kernel 1: MW[j,k,l] = sum_{n,m} Wc1[j,n]*BD[n,m]*BW[n,m,k]*BW[m,n,l]
// Grid 16 (block = j) x 256 threads (thread = (k,l)). All operands staged in
// shared via one coalesced burst -> single cold-DRAM round trip, then
// LDS-throughput-bound compute.
// ---------------------------------------------------------------------------
__global__ void k_mw(const float* __restrict__ BW, const float* __restrict__ BD,
                     const float* __restrict__ Wc1, const float* __restrict__ bc1,
                     const float* __restrict__ Boff) {
    __shared__ float sBW[4096], sBD[256], sWc1[256];
    int t = threadIdx.x;
    {
        const float4* s = (const float4*)BW;
        float4* d = (float4*)sBW;
#pragma unroll
        for (int q = 0; q < 4; q++) d[t + 256 * q] = s[t + 256 * q];
        if (t < 64)       ((float4*)sBD)[t]       = ((const float4*)BD)[t];
        else if (t < 128) ((float4*)sWc1)[t - 64] = ((const float4*)Wc1)[t - 64];
    }
    __syncthreads();

    int j = blockIdx.x;
    int k = t >> 4, l = t & 15;
    float s = 0.f;
#pragma unroll
    for (int n = 0; n < 16; n++) {
        float wjn = sWc1[j * 16 + n];
#pragma unroll
        for (int m = 0; m < 16; m++) {
            float p = wjn * sBD[n * 16 + m];
            s = fmaf(p * sBW[n * 256 + m * 16 + k], sBW[m * 256 + n * 16 + l], s);
        }
    }
    g_MW[j * 256 + t] = s;

    if (blockIdx.x == 0 && t < 16) {
        float b = bc1[t];
#pragma unroll
        for (int n = 0; n < 16; n++) b = fmaf(sWc1[t * 16 + n], Boff[n], b);
        g_bb[t] = b;
    }
}

// ---------------------------------------------------------------------------
// Kernel 2 (fused E3 + UW), 64 genes per 256-thread block.
// Phase 1 (MLP): 16 lanes/gene, weights in registers, width-16 shuffles.
// Phase 2 (UW): thread owns (j, kchunk c); 64 MW weights in registers; streams
//   16 genes from padded shared; emits fp16 uint2 per gene.
// ---------------------------------------------------------------------------
__global__ void k_e3uw(const float* __restrict__ emb,
                       const float* __restrict__ W1, const float* __restrict__ b1,
                       const float* __restrict__ W2, const float* __restrict__ b2,
                       const float* __restrict__ W3, const float* __restrict__ b3,
                       int genes) {
    __shared__ float sv[GBLK * 17];
    int t = threadIdx.x;
    int lane = t & 15;
    int base = blockIdx.x * GBLK;

    float w1r[16], w2r[16], w3r[16];
    {
        const float4* r1 = (const float4*)(W1 + lane * 16);
        const float4* r2 = (const float4*)(W2 + lane * 16);
        const float4* r3 = (const float4*)(W3 + lane * 16);
#pragma unroll
        for (int q = 0; q < 4; q++) {
            float4 a = r1[q]; w1r[q*4+0]=a.x; w1r[q*4+1]=a.y; w1r[q*4+2]=a.z; w1r[q*4+3]=a.w;
            float4 b = r2[q]; w2r[q*4+0]=b.x; w2r[q*4+1]=b.y; w2r[q*4+2]=b.z; w2r[q*4+3]=b.w;
            float4 c = r3[q]; w3r[q*4+0]=c.x; w3r[q*4+1]=c.y; w3r[q*4+2]=c.z; w3r[q*4+3]=c.w;
        }
    }
    float bias1 = b1[lane], bias2 = b2[lane], bias3 = b3[lane];

#pragma unroll
    for (int it = 0; it < 4; it++) {
        int glocal = (t >> 4) + 16 * it;
        int g = base + glocal;
        int gc = (g < genes) ? g : (genes - 1);
        float v = emb[(size_t)gc * 16 + lane];

        float h = bias1;
#pragma unroll
        for (int jj = 0; jj < 16; jj++)
            h = fmaf(w1r[jj], __shfl_sync(0xffffffffu, v, jj, 16), h);
        v = fmaxf(h, 0.f);
        h = bias2;
#pragma unroll
        for (int jj = 0; jj < 16; jj++)
            h = fmaf(w2r[jj], __shfl_sync(0xffffffffu, v, jj, 16), h);
        v = fmaxf(h, 0.f);
        h = bias3;
#pragma unroll
        for (int jj = 0; jj < 16; jj++)
            h = fmaf(w3r[jj], __shfl_sync(0xffffffffu, v, jj, 16), h);

        sv[glocal * 17 + lane] = h;
        if (g < genes)
            ((__half*)g_E3h)[(size_t)g * 16 + lane] = __float2half_rn(h);
    }
    __syncthreads();

    int j = t & 15;
    int c = (t >> 4) & 3;
    int sg = t >> 6;

    float mw[64];
    {
        const float4* mp = (const float4*)(g_MW + j * 256 + c * 64);
#pragma unroll
        for (int q = 0; q < 16; q++) {
            float4 m4 = mp[q];
            mw[q*4+0]=m4.x; mw[q*4+1]=m4.y; mw[q*4+2]=m4.z; mw[q*4+3]=m4.w;
        }
    }

    uint2* outp = (uint2*)g_UWh;
#pragma unroll
    for (int gi = 0; gi < 16; gi++) {
        int gl = gi * 4 + sg;
        int g = base + gl;
        float u0 = 0.f, u1 = 0.f, u2 = 0.f, u3 = 0.f;
#pragma unroll
        for (int l = 0; l < 16; l++) {
            float ev = sv[gl * 17 + l];
            u0 = fmaf(mw[0  + l], ev, u0);
            u1 = fmaf(mw[16 + l], ev, u1);
            u2 = fmaf(mw[32 + l], ev, u2);
            u3 = fmaf(mw[48 + l], ev, u3);
        }
        if (g < genes) {
            __half2 h01 = __floats2half2_rn(u0, u1);
            __half2 h23 = __floats2half2_rn(u2, u3);
            uint2 v;
            v.x = *(unsigned*)&h01;
            v.y = *(unsigned*)&h23;
            outp[(size_t)g * 64 + c * 16 + j] = v;
        }
    }
}

// ---------------------------------------------------------------------------
// Kernel 3: main. 16 lanes/row (2 rows/warp), lane j owns classifier unit j.
//   y_j = relu(E3h[x0] . UWh[x1,j,:] + bb[j]);  out = sum_j Wc2[j]*y_j + bc2 + sum(phenos)
// fp16 table loads, fp32 math.
// ---------------------------------------------------------------------------
__global__ void k_main(const int* __restrict__ x, const float* __restrict__ phenos,
                       const float* __restrict__ Wc2, const float* __restrict__ bc2,
                       float* __restrict__ out) {
    int t = threadIdx.x;
    int j = t & 15;
    int row = blockIdx.x * 16 + (t >> 4);

    int2 xi = ((const int2*)x)[row];
    const uint4* E = g_E3h + (size_t)xi.x * 2;
    uint4 e0 = E[0], e1 = E[1];                       // 16 halves of E3[x0]
    const uint2* U = (const uint2*)(g_UWh + (size_t)xi.y * 32);
    uint2 q0 = U[j], q1 = U[16 + j], q2 = U[32 + j], q3 = U[48 + j];

    const __half2* eh = (const __half2*)&e0;          // e0,e1 contiguous in regs? use explicit
    float z = g_bb[j];
    {
        __half2 h;
        float2 a, u;
        unsigned ue[8] = {e0.x, e0.y, e0.z, e0.w, e1.x, e1.y, e1.z, e1.w};
        unsigned uu[8] = {q0.x, q0.y, q1.x, q1.y, q2.x, q2.y, q3.x, q3.y};
#pragma unroll
        for (int q = 0; q < 8; q++) {
            h = *(__half2*)&ue[q]; a = __half22float2(h);
            h = *(__half2*)&uu[q]; u = __half22float2(h);
            z = fmaf(a.x, u.x, z);
            z = fmaf(a.y, u.y, z);
        }
    }
    (void)eh;

    float acc = fmaxf(z, 0.f) * Wc2[j];
    acc += __shfl_xor_sync(0xffffffffu, acc, 8);
    acc += __shfl_xor_sync(0xffffffffu, acc, 4);
    acc += __shfl_xor_sync(0xffffffffu, acc, 2);
    acc += __shfl_xor_sync(0xffffffffu, acc, 1);

    if (j == 0) {
        float2 ph = ((const float2*)phenos)[row];
        out[row] = acc + bc2[0] + ph.x + ph.y;
    }
}

// ---------------------------------------------------------------------------
extern "C" void kernel_launch(void* const* d_in, const int* in_sizes, int n_in,
                              void* d_out, int out_size) {
    const int*   x      = (const int*)d_in[0];
    const float* phenos = (const float*)d_in[1];
    const float* emb    = (const float*)d_in[2];
    const float* W1 = (const float*)d_in[3],  *b1 = (const float*)d_in[4];
    const float* W2 = (const float*)d_in[5],  *b2 = (const float*)d_in[6];
    const float* W3 = (const float*)d_in[7],  *b3 = (const float*)d_in[8];
    const float* BW = (const float*)d_in[9],  *BD = (const float*)d_in[10];
    const float* Boff = (const float*)d_in[11];
    const float* Wc1 = (const float*)d_in[12], *bc1 = (const float*)d_in[13];
    const float* Wc2 = (const float*)d_in[14], *bc2 = (const float*)d_in[15];
    float* out = (float*)d_out;

    int rows  = in_sizes[0] / 2;     // 262144
    int genes = in_sizes[2] / D;     // 20000

    k_mw<<<16, 256>>>(BW, BD, Wc1, bc1, Boff);
    k_e3uw<<<(genes + GBLK - 1) / GBLK, 256>>>(emb, W1, b1, W2, b2, W3, b3, genes);
    k_main<<<rows / 16, 256>>>(x, phenos, Wc2, bc2, out);
}